// round 2
// baseline (speedup 1.0000x reference)
#include <cuda_runtime.h>
#include <math.h>

#define B_  2
#define L_  1024
#define D_  1024
#define H_  16
#define R_  16
#define DK_ 64
#define F_  4096
#define NL_ 4
#define ROWS_ (B_*L_)

// ---------------- scratch (no runtime allocation allowed) ----------------
__device__ float g_x  [ROWS_*D_];
__device__ float g_h  [ROWS_*D_];
__device__ float g_q  [ROWS_*D_];
__device__ float g_k  [ROWS_*D_];
__device__ float g_v  [ROWS_*D_];
__device__ float g_ctx[ROWS_*D_];
__device__ float g_ff [ROWS_*F_];

// ---------------- LayerNorm: one block per row, D=1024, 256 thr ----------
__global__ __launch_bounds__(256) void ln_kernel(
    const float* __restrict__ x, const float* __restrict__ g,
    const float* __restrict__ b, float* __restrict__ out)
{
    int row = blockIdx.x;
    int t = threadIdx.x;
    const float4* xr = (const float4*)(x + (size_t)row * D_);
    float4 v = xr[t];

    __shared__ float red[8];
    // mean
    float s = v.x + v.y + v.z + v.w;
    #pragma unroll
    for (int o = 16; o; o >>= 1) s += __shfl_xor_sync(0xffffffffu, s, o);
    if ((t & 31) == 0) red[t >> 5] = s;
    __syncthreads();
    float tot = red[0];
    #pragma unroll
    for (int w = 1; w < 8; w++) tot += red[w];
    float mu = tot * (1.0f / D_);
    float dx = v.x - mu, dy = v.y - mu, dz = v.z - mu, dw = v.w - mu;
    __syncthreads();
    // variance
    float s2 = dx*dx + dy*dy + dz*dz + dw*dw;
    #pragma unroll
    for (int o = 16; o; o >>= 1) s2 += __shfl_xor_sync(0xffffffffu, s2, o);
    if ((t & 31) == 0) red[t >> 5] = s2;
    __syncthreads();
    float tot2 = red[0];
    #pragma unroll
    for (int w = 1; w < 8; w++) tot2 += red[w];
    float rstd = rsqrtf(tot2 * (1.0f / D_) + 1e-5f);

    float4 gv = ((const float4*)g)[t];
    float4 bv = ((const float4*)b)[t];
    float4 o4;
    o4.x = dx * rstd * gv.x + bv.x;
    o4.y = dy * rstd * gv.y + bv.y;
    o4.z = dz * rstd * gv.z + bv.z;
    o4.w = dw * rstd * gv.w + bv.w;
    ((float4*)(out + (size_t)row * D_))[t] = o4;
}

// ---------------- SGEMM 128x128x8, fused bias/gelu/residual --------------
#define BM 128
#define BN 128
#define BK 8
#define TM 8
#define TN 8

__device__ __forceinline__ float gelu_f(float x) {
    float x3 = x * x * x;
    return 0.5f * x * (1.0f + tanhf(0.7978845608028654f * (x + 0.044715f * x3)));
}

__global__ __launch_bounds__(256, 1) void sgemm_ep(
    const float* __restrict__ A, const float* __restrict__ Bm,
    const float* __restrict__ bias, const float* __restrict__ res,
    float* __restrict__ C, int M, int N, int K, int do_gelu)
{
    __shared__ float As[BK][BM];
    __shared__ float Bs[BK][BN];
    int tid = threadIdx.x;
    int tx = tid & 15, ty = tid >> 4;

    const float* Ab = A + (size_t)blockIdx.y * BM * K;
    const float* Bb = Bm + blockIdx.x * BN;

    int arow = tid >> 1, acol = (tid & 1) * 4;   // A tile: 128 rows x 8 cols
    int brow = tid >> 5, bcol = (tid & 31) * 4;  // B tile: 8 rows x 128 cols

    float acc[TM][TN] = {};

    for (int k0 = 0; k0 < K; k0 += BK) {
        float4 a4 = *(const float4*)(Ab + (size_t)arow * K + k0 + acol);
        As[acol + 0][arow] = a4.x;
        As[acol + 1][arow] = a4.y;
        As[acol + 2][arow] = a4.z;
        As[acol + 3][arow] = a4.w;
        *(float4*)(&Bs[brow][bcol]) =
            *(const float4*)(Bb + (size_t)(k0 + brow) * N + bcol);
        __syncthreads();

        #pragma unroll
        for (int kk = 0; kk < BK; kk++) {
            float ar[TM], br[TN];
            #pragma unroll
            for (int i = 0; i < TM; i++) ar[i] = As[kk][ty * TM + i];
            #pragma unroll
            for (int j = 0; j < TN; j++) br[j] = Bs[kk][tx * TN + j];
            #pragma unroll
            for (int i = 0; i < TM; i++)
                #pragma unroll
                for (int j = 0; j < TN; j++)
                    acc[i][j] = fmaf(ar[i], br[j], acc[i][j]);
        }
        __syncthreads();
    }

    int row0 = blockIdx.y * BM + ty * TM;
    int col0 = blockIdx.x * BN + tx * TN;
    #pragma unroll
    for (int i = 0; i < TM; i++) {
        size_t ro = (size_t)(row0 + i) * N;
        #pragma unroll
        for (int j = 0; j < TN; j += 4) {
            int col = col0 + j;
            float4 bi = *(const float4*)(bias + col);
            float4 o;
            o.x = acc[i][j + 0] + bi.x;
            o.y = acc[i][j + 1] + bi.y;
            o.z = acc[i][j + 2] + bi.z;
            o.w = acc[i][j + 3] + bi.w;
            if (do_gelu) {
                o.x = gelu_f(o.x); o.y = gelu_f(o.y);
                o.z = gelu_f(o.z); o.w = gelu_f(o.w);
            }
            if (res) {
                float4 r = *(const float4*)(res + ro + col);
                o.x += r.x; o.y += r.y; o.z += r.z; o.w += r.w;
            }
            *(float4*)(C + ro + col) = o;
        }
    }
}

// ---------------- tree-relative attention: one warp per (b,h,l) ----------
__global__ __launch_bounds__(256) void attn_kernel(
    const float* __restrict__ q, const float* __restrict__ k,
    const float* __restrict__ v, const int* __restrict__ pos,
    const float* __restrict__ rq, const float* __restrict__ rk,
    const float* __restrict__ rv, float* __restrict__ ctx)
{
    int gw   = blockIdx.x * (blockDim.x >> 5) + (threadIdx.x >> 5);
    int lane = threadIdx.x & 31;
    int l  = gw & (L_ - 1);
    int bh = gw >> 10;          // log2(L_)
    int h  = bh & (H_ - 1);
    int b  = bh >> 4;           // log2(H_)

    size_t qoff = (size_t)(b * L_ + l) * D_ + h * DK_ + lane * 2;
    float2 qv = *(const float2*)(q + qoff);
    const int* pp = pos + ((size_t)(b * H_ + h) * R_) * L_ + l;

    float sc[R_];
    int   idxs[R_];
    #pragma unroll
    for (int r = 0; r < R_; r++) {
        int idx = pp[(size_t)r * L_];
        idxs[r] = idx;
        float2 rqv = *(const float2*)(rq + (h * R_ + r) * DK_ + lane * 2);
        float2 rkv = *(const float2*)(rk + (h * R_ + r) * DK_ + lane * 2);
        float2 kg  = *(const float2*)(k + (size_t)(b * L_ + idx) * D_ + h * DK_ + lane * 2);
        float p = (qv.x + rqv.x) * kg.x + (qv.y + rqv.y) * kg.y
                +  qv.x * rkv.x + qv.y * rkv.y;
        #pragma unroll
        for (int o = 16; o; o >>= 1) p += __shfl_xor_sync(0xffffffffu, p, o);
        sc[r] = (idx != l) ? p * 0.125f : -1e9f;
    }

    float m = sc[0];
    #pragma unroll
    for (int r = 1; r < R_; r++) m = fmaxf(m, sc[r]);
    float s = 0.0f;
    #pragma unroll
    for (int r = 0; r < R_; r++) { sc[r] = __expf(sc[r] - m); s += sc[r]; }
    float inv = 1.0f / s;

    float ax = 0.0f, ay = 0.0f;
    #pragma unroll
    for (int r = 0; r < R_; r++) {
        float a = sc[r] * inv;
        float2 rvv = *(const float2*)(rv + (h * R_ + r) * DK_ + lane * 2);
        float2 vg  = *(const float2*)(v + (size_t)(b * L_ + idxs[r]) * D_ + h * DK_ + lane * 2);
        ax = fmaf(a, vg.x + rvv.x, ax);
        ay = fmaf(a, vg.y + rvv.y, ay);
    }
    *(float2*)(ctx + qoff) = make_float2(ax, ay);
}

// ---------------- host orchestration -------------------------------------
extern "C" void kernel_launch(void* const* d_in, const int* in_sizes, int n_in,
                              void* d_out, int out_size)
{
    const float* emb    = (const float*)d_in[0];
    const int*   pos    = (const int*)  d_in[1];
    const float* rel_q  = (const float*)d_in[2];
    const float* rel_k  = (const float*)d_in[3];
    const float* rel_v  = (const float*)d_in[4];
    const float* attn_w = (const float*)d_in[5];
    const float* attn_b = (const float*)d_in[6];
    const float* ff_w1  = (const float*)d_in[7];
    const float* ff_b1  = (const float*)d_in[8];
    const float* ff_w2  = (const float*)d_in[9];
    const float* ff_b2  = (const float*)d_in[10];
    const float* ln_g   = (const float*)d_in[11];
    const float* ln_b   = (const float*)d_in[12];
    const float* fin_g  = (const float*)d_in[13];
    const float* fin_b  = (const float*)d_in[14];
    float* out = (float*)d_out;

    float *x, *h, *q, *k, *v, *ctx, *ff;
    cudaGetSymbolAddress((void**)&x,   g_x);
    cudaGetSymbolAddress((void**)&h,   g_h);
    cudaGetSymbolAddress((void**)&q,   g_q);
    cudaGetSymbolAddress((void**)&k,   g_k);
    cudaGetSymbolAddress((void**)&v,   g_v);
    cudaGetSymbolAddress((void**)&ctx, g_ctx);
    cudaGetSymbolAddress((void**)&ff,  g_ff);

    dim3 gD(D_ / BN, ROWS_ / BM);   // (8, 16)
    dim3 gF(F_ / BN, ROWS_ / BM);   // (32, 16)
    int attn_blocks = (B_ * H_ * L_) / 8;   // 8 warps per block

    for (int i = 0; i < NL_; i++) {
        const float* xin = (i == 0) ? emb : x;
        const float* W  = attn_w + (size_t)i * 4 * D_ * D_;
        const float* Bb = attn_b + (size_t)i * 4 * D_;

        // pre-norm 1
        ln_kernel<<<ROWS_, 256>>>(xin, ln_g + (size_t)(i * 2) * D_,
                                       ln_b + (size_t)(i * 2) * D_, h);
        // q, k, v projections
        sgemm_ep<<<gD, 256>>>(h, W,                 Bb,          nullptr, q, ROWS_, D_, D_, 0);
        sgemm_ep<<<gD, 256>>>(h, W + (size_t)D_*D_,   Bb + D_,     nullptr, k, ROWS_, D_, D_, 0);
        sgemm_ep<<<gD, 256>>>(h, W + (size_t)2*D_*D_, Bb + 2*D_,   nullptr, v, ROWS_, D_, D_, 0);
        // tree-relative attention
        attn_kernel<<<attn_blocks, 256>>>(q, k, v, pos, rel_q, rel_k, rel_v, ctx);
        // output projection + residual (bootstraps residual stream from emb at i==0)
        sgemm_ep<<<gD, 256>>>(ctx, W + (size_t)3*D_*D_, Bb + 3*D_, xin, x, ROWS_, D_, D_, 0);
        // pre-norm 2
        ln_kernel<<<ROWS_, 256>>>(x, ln_g + (size_t)(i * 2 + 1) * D_,
                                     ln_b + (size_t)(i * 2 + 1) * D_, h);
        // FFN
        sgemm_ep<<<gF, 256>>>(h,  ff_w1 + (size_t)i * D_ * F_, ff_b1 + (size_t)i * F_,
                              nullptr, ff, ROWS_, F_, D_, 1);
        sgemm_ep<<<gD, 256>>>(ff, ff_w2 + (size_t)i * F_ * D_, ff_b2 + (size_t)i * D_,
                              x, x, ROWS_, D_, F_, 0);
    }
    // final layernorm -> output
    ln_kernel<<<ROWS_, 256>>>(x, fin_g, fin_b, out);
}

// round 4
// speedup vs baseline: 4.2342x; 4.2342x over previous
#include <cuda_runtime.h>
#include <math.h>
#include <stdint.h>

#define B_  2
#define L_  1024
#define D_  1024
#define H_  16
#define R_  16
#define DK_ 64
#define F_  4096
#define NL_ 4
#define ROWS_ (B_*L_)

// ---------------- scratch (no runtime allocation allowed) ----------------
__device__ float g_x  [ROWS_*D_];
__device__ float g_h  [ROWS_*D_];
__device__ float g_q  [ROWS_*D_];
__device__ float g_k  [ROWS_*D_];
__device__ float g_v  [ROWS_*D_];
__device__ float g_ctx[ROWS_*D_];
__device__ float g_ff [ROWS_*F_];
__device__ float g_wt_attn[(size_t)NL_*4*D_*D_];
__device__ float g_wt_ff1 [(size_t)NL_*D_*F_];
__device__ float g_wt_ff2 [(size_t)NL_*F_*D_];

// ---------------- helpers -------------------------------------------------
__device__ __forceinline__ uint32_t smem_to_u32(const void* p) {
    uint32_t a;
    asm("{ .reg .u64 t; cvta.to.shared.u64 t, %1; cvt.u32.u64 %0, t; }" : "=r"(a) : "l"(p));
    return a;
}
__device__ __forceinline__ float tf32r(float x) {
    float r; asm("cvt.rna.tf32.f32 %0, %1;" : "=f"(r) : "f"(x)); return r;
}
__device__ __forceinline__ void cp16(uint32_t dst, const void* src) {
    asm volatile("cp.async.cg.shared.global [%0], [%1], 16;" :: "r"(dst), "l"(src));
}
__device__ __forceinline__ void ldsm_x4(uint32_t* r, uint32_t addr) {
    asm volatile("ldmatrix.sync.aligned.m8n8.x4.shared.b16 {%0,%1,%2,%3}, [%4];"
        : "=r"(r[0]), "=r"(r[1]), "=r"(r[2]), "=r"(r[3]) : "r"(addr));
}
__device__ __forceinline__ void ldsm_x2(uint32_t* r, uint32_t addr) {
    asm volatile("ldmatrix.sync.aligned.m8n8.x2.shared.b16 {%0,%1}, [%2];"
        : "=r"(r[0]), "=r"(r[1]) : "r"(addr));
}
__device__ __forceinline__ void mma_tf32(float* c, const uint32_t* a, const uint32_t* b) {
    asm volatile(
        "mma.sync.aligned.m16n8k8.row.col.f32.tf32.tf32.f32 "
        "{%0,%1,%2,%3}, {%4,%5,%6,%7}, {%8,%9}, {%0,%1,%2,%3};"
        : "+f"(c[0]), "+f"(c[1]), "+f"(c[2]), "+f"(c[3])
        : "r"(a[0]), "r"(a[1]), "r"(a[2]), "r"(a[3]), "r"(b[0]), "r"(b[1]));
}
__device__ __forceinline__ float gelu_f(float x) {
    float x3 = x * x * x;
    return 0.5f * x * (1.0f + tanhf(0.7978845608028654f * (x + 0.044715f * x3)));
}

// ---------------- weight transpose (src [K][N] -> dst [N][K], tf32-rounded) ----
__global__ __launch_bounds__(256) void transpose_k(
    const float* __restrict__ src, float* __restrict__ dst, int K, int N)
{
    __shared__ float t[32][33];
    src += (size_t)blockIdx.z * K * N;
    dst += (size_t)blockIdx.z * K * N;
    int n0 = blockIdx.x * 32, k0 = blockIdx.y * 32;
    int tx = threadIdx.x, ty = threadIdx.y;
    #pragma unroll
    for (int i = 0; i < 32; i += 8)
        t[ty + i][tx] = tf32r(src[(size_t)(k0 + ty + i) * N + n0 + tx]);
    __syncthreads();
    #pragma unroll
    for (int i = 0; i < 32; i += 8)
        dst[(size_t)(n0 + ty + i) * K + k0 + tx] = t[tx][ty + i];
}

// ---------------- tf32 mma.sync GEMM: C[M,N] = A[M,K] * Bt[N,K]^T ----------
// CTA 128x128, 4 warps (64x64 each), BK=32, 3-stage cp.async pipeline.
// smem rows padded: 32 floats + 4 pad = 144 bytes (16B aligned, conflict-free)
#define BKG   32
#define ROWB  144            // bytes per smem row
#define HALF  (128*ROWB)     // 18432 bytes (A or B tile)
#define STAGE (2*HALF)       // 36864
#define NSTG  3
#define GEMM_SMEM (NSTG*STAGE)   // 110592

__global__ __launch_bounds__(128, 1) void tc_gemm(
    const float* __restrict__ A, const float* __restrict__ Bt,
    const float* __restrict__ bias, const float* __restrict__ res,
    float* __restrict__ C, int M, int N, int K, int do_gelu)
{
    extern __shared__ char smem[];
    const uint32_t sb = smem_to_u32(smem);
    const int tid  = threadIdx.x;
    const int wid  = tid >> 5;
    const int lane = tid & 31;

    const int m0 = blockIdx.y * 128;
    const int n0 = blockIdx.x * 128;
    const int KT = K / BKG;

    const int warp_m = (wid >> 1) * 64;
    const int warp_n = (wid & 1) * 64;

    // ldmatrix per-lane base offsets (within a stage half)
    const int agrp = lane >> 3;                 // 0..3
    const uint32_t a_off = (uint32_t)(warp_m + (agrp & 1) * 8 + (lane & 7)) * ROWB
                         + (uint32_t)(agrp >> 1) * 16;
    const uint32_t b_off = (uint32_t)(warp_n + (lane & 7)) * ROWB
                         + (uint32_t)((lane >> 3) & 1) * 16;

    float acc[4][8][4];
    #pragma unroll
    for (int i = 0; i < 4; i++)
        #pragma unroll
        for (int j = 0; j < 8; j++)
            #pragma unroll
            for (int v = 0; v < 4; v++) acc[i][j][v] = 0.0f;

    // --- stage loader: 8 A-chunks + 8 B-chunks of 16B per thread ---
    auto load_stage = [&](int s, int kt) {
        uint32_t dA = sb + s * STAGE;
        uint32_t dB = dA + HALF;
        int kbase = kt * BKG;
        #pragma unroll
        for (int i = 0; i < 8; i++) {
            int c = tid + i * 128;             // 0..1023
            int row = c >> 3, kk = c & 7;
            cp16(dA + row * ROWB + kk * 16,
                 A + (size_t)(m0 + row) * K + kbase + kk * 4);
        }
        #pragma unroll
        for (int i = 0; i < 8; i++) {
            int c = tid + i * 128;
            int row = c >> 3, kk = c & 7;
            cp16(dB + row * ROWB + kk * 16,
                 Bt + (size_t)(n0 + row) * K + kbase + kk * 4);
        }
    };

    // prologue: stages 0,1
    load_stage(0, 0);
    asm volatile("cp.async.commit_group;");
    if (KT > 1) load_stage(1, 1);
    asm volatile("cp.async.commit_group;");

    for (int kt = 0; kt < KT; kt++) {
        asm volatile("cp.async.wait_group 1;");
        __syncthreads();

        // issue next stage (overwrites stage consumed 2 iters ago; safe after sync)
        if (kt + 2 < KT) load_stage((kt + 2) % NSTG, kt + 2);
        asm volatile("cp.async.commit_group;");

        int s = kt % NSTG;
        uint32_t sA = sb + s * STAGE;
        uint32_t sB = sA + HALF;

        #pragma unroll
        for (int k8 = 0; k8 < 4; k8++) {
            uint32_t a[4][4], b[8][2];
            #pragma unroll
            for (int mt = 0; mt < 4; mt++)
                ldsm_x4(a[mt], sA + a_off + (uint32_t)mt * (16 * ROWB) + k8 * 32);
            #pragma unroll
            for (int nt = 0; nt < 8; nt++)
                ldsm_x2(b[nt], sB + b_off + (uint32_t)nt * (8 * ROWB) + k8 * 32);
            #pragma unroll
            for (int mt = 0; mt < 4; mt++)
                #pragma unroll
                for (int nt = 0; nt < 8; nt++)
                    mma_tf32(acc[mt][nt], a[mt], b[nt]);
        }
        __syncthreads();
    }

    // ---------------- epilogue ----------------
    const int rbase = m0 + warp_m + (lane >> 2);
    const int cbase = n0 + warp_n + 2 * (lane & 3);
    #pragma unroll
    for (int mt = 0; mt < 4; mt++) {
        #pragma unroll
        for (int nt = 0; nt < 8; nt++) {
            int col = cbase + nt * 8;
            float2 bi = *(const float2*)(bias + col);
            #pragma unroll
            for (int half = 0; half < 2; half++) {
                int row = rbase + mt * 16 + half * 8;
                size_t ro = (size_t)row * N + col;
                float ox = acc[mt][nt][2 * half + 0] + bi.x;
                float oy = acc[mt][nt][2 * half + 1] + bi.y;
                if (do_gelu) {
                    ox = tf32r(gelu_f(ox));   // ff output feeds next tf32 GEMM
                    oy = tf32r(gelu_f(oy));
                }
                if (res) {
                    float2 rv = *(const float2*)(res + ro);
                    ox += rv.x; oy += rv.y;
                }
                *(float2*)(C + ro) = make_float2(ox, oy);
            }
        }
    }
}

// ---------------- LayerNorm: one block per row, D=1024, 256 thr ----------
__global__ __launch_bounds__(256) void ln_kernel(
    const float* __restrict__ x, const float* __restrict__ g,
    const float* __restrict__ b, float* __restrict__ out, int round_tf32)
{
    int row = blockIdx.x;
    int t = threadIdx.x;
    const float4* xr = (const float4*)(x + (size_t)row * D_);
    float4 v = xr[t];

    __shared__ float red[8];
    float s = v.x + v.y + v.z + v.w;
    #pragma unroll
    for (int o = 16; o; o >>= 1) s += __shfl_xor_sync(0xffffffffu, s, o);
    if ((t & 31) == 0) red[t >> 5] = s;
    __syncthreads();
    float tot = red[0];
    #pragma unroll
    for (int w = 1; w < 8; w++) tot += red[w];
    float mu = tot * (1.0f / D_);
    float dx = v.x - mu, dy = v.y - mu, dz = v.z - mu, dw = v.w - mu;
    __syncthreads();
    float s2 = dx*dx + dy*dy + dz*dz + dw*dw;
    #pragma unroll
    for (int o = 16; o; o >>= 1) s2 += __shfl_xor_sync(0xffffffffu, s2, o);
    if ((t & 31) == 0) red[t >> 5] = s2;
    __syncthreads();
    float tot2 = red[0];
    #pragma unroll
    for (int w = 1; w < 8; w++) tot2 += red[w];
    float rstd = rsqrtf(tot2 * (1.0f / D_) + 1e-5f);

    float4 gv = ((const float4*)g)[t];
    float4 bv = ((const float4*)b)[t];
    float4 o4;
    o4.x = dx * rstd * gv.x + bv.x;
    o4.y = dy * rstd * gv.y + bv.y;
    o4.z = dz * rstd * gv.z + bv.z;
    o4.w = dw * rstd * gv.w + bv.w;
    if (round_tf32) {
        o4.x = tf32r(o4.x); o4.y = tf32r(o4.y);
        o4.z = tf32r(o4.z); o4.w = tf32r(o4.w);
    }
    ((float4*)(out + (size_t)row * D_))[t] = o4;
}

// ---------------- tree-relative attention: one warp per (b,h,l) ----------
__global__ __launch_bounds__(256) void attn_kernel(
    const float* __restrict__ q, const float* __restrict__ k,
    const float* __restrict__ v, const int* __restrict__ pos,
    const float* __restrict__ rq, const float* __restrict__ rk,
    const float* __restrict__ rv, float* __restrict__ ctx)
{
    int gw   = blockIdx.x * (blockDim.x >> 5) + (threadIdx.x >> 5);
    int lane = threadIdx.x & 31;
    int l  = gw & (L_ - 1);
    int bh = gw >> 10;
    int h  = bh & (H_ - 1);
    int b  = bh >> 4;

    size_t qoff = (size_t)(b * L_ + l) * D_ + h * DK_ + lane * 2;
    float2 qv = *(const float2*)(q + qoff);
    const int* pp = pos + ((size_t)(b * H_ + h) * R_) * L_ + l;

    float sc[R_];
    int   idxs[R_];
    #pragma unroll
    for (int r = 0; r < R_; r++) {
        int idx = pp[(size_t)r * L_];
        idxs[r] = idx;
        float2 rqv = *(const float2*)(rq + (h * R_ + r) * DK_ + lane * 2);
        float2 rkv = *(const float2*)(rk + (h * R_ + r) * DK_ + lane * 2);
        float2 kg  = *(const float2*)(k + (size_t)(b * L_ + idx) * D_ + h * DK_ + lane * 2);
        float p = (qv.x + rqv.x) * kg.x + (qv.y + rqv.y) * kg.y
                +  qv.x * rkv.x + qv.y * rkv.y;
        #pragma unroll
        for (int o = 16; o; o >>= 1) p += __shfl_xor_sync(0xffffffffu, p, o);
        sc[r] = (idx != l) ? p * 0.125f : -1e9f;
    }

    float m = sc[0];
    #pragma unroll
    for (int r = 1; r < R_; r++) m = fmaxf(m, sc[r]);
    float s = 0.0f;
    #pragma unroll
    for (int r = 0; r < R_; r++) { sc[r] = __expf(sc[r] - m); s += sc[r]; }
    float inv = 1.0f / s;

    float ax = 0.0f, ay = 0.0f;
    #pragma unroll
    for (int r = 0; r < R_; r++) {
        float a = sc[r] * inv;
        float2 rvv = *(const float2*)(rv + (h * R_ + r) * DK_ + lane * 2);
        float2 vg  = *(const float2*)(v + (size_t)(b * L_ + idxs[r]) * D_ + h * DK_ + lane * 2);
        ax = fmaf(a, vg.x + rvv.x, ax);
        ay = fmaf(a, vg.y + rvv.y, ay);
    }
    // ctx feeds a tf32 GEMM -> round here
    *(float2*)(ctx + qoff) = make_float2(tf32r(ax), tf32r(ay));
}

// ---------------- host orchestration -------------------------------------
extern "C" void kernel_launch(void* const* d_in, const int* in_sizes, int n_in,
                              void* d_out, int out_size)
{
    const float* emb    = (const float*)d_in[0];
    const int*   pos    = (const int*)  d_in[1];
    const float* rel_q  = (const float*)d_in[2];
    const float* rel_k  = (const float*)d_in[3];
    const float* rel_v  = (const float*)d_in[4];
    const float* attn_w = (const float*)d_in[5];
    const float* attn_b = (const float*)d_in[6];
    const float* ff_w1  = (const float*)d_in[7];
    const float* ff_b1  = (const float*)d_in[8];
    const float* ff_w2  = (const float*)d_in[9];
    const float* ff_b2  = (const float*)d_in[10];
    const float* ln_g   = (const float*)d_in[11];
    const float* ln_b   = (const float*)d_in[12];
    const float* fin_g  = (const float*)d_in[13];
    const float* fin_b  = (const float*)d_in[14];
    float* out = (float*)d_out;

    float *x, *h, *q, *k, *v, *ctx, *ff, *wta, *wtf1, *wtf2;
    cudaGetSymbolAddress((void**)&x,    g_x);
    cudaGetSymbolAddress((void**)&h,    g_h);
    cudaGetSymbolAddress((void**)&q,    g_q);
    cudaGetSymbolAddress((void**)&k,    g_k);
    cudaGetSymbolAddress((void**)&v,    g_v);
    cudaGetSymbolAddress((void**)&ctx,  g_ctx);
    cudaGetSymbolAddress((void**)&ff,   g_ff);
    cudaGetSymbolAddress((void**)&wta,  g_wt_attn);
    cudaGetSymbolAddress((void**)&wtf1, g_wt_ff1);
    cudaGetSymbolAddress((void**)&wtf2, g_wt_ff2);

    static bool attr_done = false;
    if (!attr_done) {
        cudaFuncSetAttribute(tc_gemm, cudaFuncAttributeMaxDynamicSharedMemorySize, GEMM_SMEM);
        attr_done = true;
    }

    // ---- weight transposes (tf32-rounded): W[K][N] -> Wt[N][K] ----
    transpose_k<<<dim3(D_/32, D_/32, NL_*4), dim3(32,8)>>>(attn_w, wta,  D_, D_);
    transpose_k<<<dim3(F_/32, D_/32, NL_),   dim3(32,8)>>>(ff_w1,  wtf1, D_, F_);
    transpose_k<<<dim3(D_/32, F_/32, NL_),   dim3(32,8)>>>(ff_w2,  wtf2, F_, D_);

    dim3 gD(D_/128, ROWS_/128);   // (8, 16)
    dim3 gF(F_/128, ROWS_/128);   // (32, 16)
    int attn_blocks = (B_ * H_ * L_) / 8;

    for (int i = 0; i < NL_; i++) {
        const float* xin = (i == 0) ? emb : x;
        const float* Wt = wta + (size_t)i * 4 * D_ * D_;
        const float* Bb = attn_b + (size_t)i * 4 * D_;

        ln_kernel<<<ROWS_, 256>>>(xin, ln_g + (size_t)(i*2) * D_, ln_b + (size_t)(i*2) * D_, h, 1);

        tc_gemm<<<gD, 128, GEMM_SMEM>>>(h, Wt,                   Bb,        nullptr, q, ROWS_, D_, D_, 0);
        tc_gemm<<<gD, 128, GEMM_SMEM>>>(h, Wt + (size_t)D_*D_,   Bb + D_,   nullptr, k, ROWS_, D_, D_, 0);
        tc_gemm<<<gD, 128, GEMM_SMEM>>>(h, Wt + (size_t)2*D_*D_, Bb + 2*D_, nullptr, v, ROWS_, D_, D_, 0);

        attn_kernel<<<attn_blocks, 256>>>(q, k, v, pos, rel_q, rel_k, rel_v, ctx);

        tc_gemm<<<gD, 128, GEMM_SMEM>>>(ctx, Wt + (size_t)3*D_*D_, Bb + 3*D_, xin, x, ROWS_, D_, D_, 0);

        ln_kernel<<<ROWS_, 256>>>(x, ln_g + (size_t)(i*2+1) * D_, ln_b + (size_t)(i*2+1) * D_, h, 1);

        tc_gemm<<<gF, 128, GEMM_SMEM>>>(h,  wtf1 + (size_t)i * D_ * F_, ff_b1 + (size_t)i * F_,
                                        nullptr, ff, ROWS_, F_, D_, 1);
        tc_gemm<<<gD, 128, GEMM_SMEM>>>(ff, wtf2 + (size_t)i * F_ * D_, ff_b2 + (size_t)i * D_,
                                        x, x, ROWS_, D_, F_, 0);
    }
    ln_kernel<<<ROWS_, 256>>>(x, fin_g, fin_b, out, 0);
}

// round 5
// speedup vs baseline: 4.4040x; 1.0401x over previous
#include <cuda_runtime.h>
#include <math.h>
#include <stdint.h>

#define B_  2
#define L_  1024
#define D_  1024
#define H_  16
#define R_  16
#define DK_ 64
#define F_  4096
#define NL_ 4
#define ROWS_ (B_*L_)
#define QSTR (3*D_)

// ---------------- scratch (no runtime allocation allowed) ----------------
__device__ float g_x  [ROWS_*D_];
__device__ float g_h  [ROWS_*D_];
__device__ float g_qkv[ROWS_*3*D_];
__device__ float g_ctx[ROWS_*D_];
__device__ float g_ff [ROWS_*F_];
__device__ float g_wt_attn[(size_t)NL_*4*D_*D_];
__device__ float g_wt_ff1 [(size_t)NL_*D_*F_];
__device__ float g_wt_ff2 [(size_t)NL_*F_*D_];

// ---------------- helpers -------------------------------------------------
__device__ __forceinline__ uint32_t smem_to_u32(const void* p) {
    uint32_t a;
    asm("{ .reg .u64 t; cvta.to.shared.u64 t, %1; cvt.u32.u64 %0, t; }" : "=r"(a) : "l"(p));
    return a;
}
__device__ __forceinline__ float tf32r(float x) {
    float r; asm("cvt.rna.tf32.f32 %0, %1;" : "=f"(r) : "f"(x)); return r;
}
__device__ __forceinline__ void cp16(uint32_t dst, const void* src) {
    asm volatile("cp.async.cg.shared.global [%0], [%1], 16;" :: "r"(dst), "l"(src));
}
__device__ __forceinline__ void ldsm_x4(uint32_t* r, uint32_t addr) {
    asm volatile("ldmatrix.sync.aligned.m8n8.x4.shared.b16 {%0,%1,%2,%3}, [%4];"
        : "=r"(r[0]), "=r"(r[1]), "=r"(r[2]), "=r"(r[3]) : "r"(addr));
}
__device__ __forceinline__ void ldsm_x2(uint32_t* r, uint32_t addr) {
    asm volatile("ldmatrix.sync.aligned.m8n8.x2.shared.b16 {%0,%1}, [%2];"
        : "=r"(r[0]), "=r"(r[1]) : "r"(addr));
}
__device__ __forceinline__ void mma_tf32(float* c, const uint32_t* a, const uint32_t* b) {
    asm volatile(
        "mma.sync.aligned.m16n8k8.row.col.f32.tf32.tf32.f32 "
        "{%0,%1,%2,%3}, {%4,%5,%6,%7}, {%8,%9}, {%0,%1,%2,%3};"
        : "+f"(c[0]), "+f"(c[1]), "+f"(c[2]), "+f"(c[3])
        : "r"(a[0]), "r"(a[1]), "r"(a[2]), "r"(a[3]), "r"(b[0]), "r"(b[1]));
}
__device__ __forceinline__ float gelu_f(float x) {
    float x3 = x * x * x;
    return 0.5f * x * (1.0f + tanhf(0.7978845608028654f * (x + 0.044715f * x3)));
}

// ---------------- weight transpose (src [K][N] -> dst [N][K], tf32-rounded) ----
__global__ __launch_bounds__(256) void transpose_k(
    const float* __restrict__ src, float* __restrict__ dst, int K, int N)
{
    __shared__ float t[32][33];
    src += (size_t)blockIdx.z * K * N;
    dst += (size_t)blockIdx.z * K * N;
    int n0 = blockIdx.x * 32, k0 = blockIdx.y * 32;
    int tx = threadIdx.x, ty = threadIdx.y;
    #pragma unroll
    for (int i = 0; i < 32; i += 8)
        t[ty + i][tx] = tf32r(src[(size_t)(k0 + ty + i) * N + n0 + tx]);
    __syncthreads();
    #pragma unroll
    for (int i = 0; i < 32; i += 8)
        dst[(size_t)(n0 + ty + i) * K + k0 + tx] = t[tx][ty + i];
}

// ---------------- tf32 mma.sync GEMM: C[M,N] = A[M,K] * Bt[N,K]^T ----------
// CTA 128x128, 8 warps (warp tile 64x32, 2x4 grid), BK=32, 4-stage cp.async.
#define BKG   32
#define ROWB  144            // bytes per smem row (32 floats + 16B pad)
#define HALF  (128*ROWB)     // 18432 bytes (A or B tile)
#define STAGE (2*HALF)       // 36864
#define NSTG  4
#define GEMM_SMEM (NSTG*STAGE)   // 147456

__global__ __launch_bounds__(256, 1) void tc_gemm(
    const float* __restrict__ A, const float* __restrict__ Bt,
    const float* __restrict__ bias, const float* __restrict__ res,
    float* __restrict__ C, int M, int N, int K, int do_gelu)
{
    extern __shared__ char smem[];
    const uint32_t sb = smem_to_u32(smem);
    const int tid  = threadIdx.x;
    const int wid  = tid >> 5;
    const int lane = tid & 31;

    const int m0 = blockIdx.y * 128;
    const int n0 = blockIdx.x * 128;
    const int KT = K / BKG;

    const int warp_m = (wid >> 2) * 64;      // 0 or 64
    const int warp_n = (wid & 3) * 32;       // 0,32,64,96

    const int agrp = lane >> 3;
    const uint32_t a_off = (uint32_t)(warp_m + (agrp & 1) * 8 + (lane & 7)) * ROWB
                         + (uint32_t)(agrp >> 1) * 16;
    const uint32_t b_off = (uint32_t)(warp_n + (lane & 7)) * ROWB
                         + (uint32_t)((lane >> 3) & 1) * 16;

    float acc[4][4][4];
    #pragma unroll
    for (int i = 0; i < 4; i++)
        #pragma unroll
        for (int j = 0; j < 4; j++)
            #pragma unroll
            for (int v = 0; v < 4; v++) acc[i][j][v] = 0.0f;

    // --- stage loader: 4 A-chunks + 4 B-chunks of 16B per thread (256 thr) ---
    auto load_stage = [&](int kt) {
        if (kt >= KT) return;
        int s = kt & (NSTG - 1);
        uint32_t dA = sb + s * STAGE;
        uint32_t dB = dA + HALF;
        int kbase = kt * BKG;
        #pragma unroll
        for (int i = 0; i < 4; i++) {
            int c = tid + i * 256;             // 0..1023
            int row = c >> 3, kk = c & 7;
            cp16(dA + row * ROWB + kk * 16,
                 A + (size_t)(m0 + row) * K + kbase + kk * 4);
        }
        #pragma unroll
        for (int i = 0; i < 4; i++) {
            int c = tid + i * 256;
            int row = c >> 3, kk = c & 7;
            cp16(dB + row * ROWB + kk * 16,
                 Bt + (size_t)(n0 + row) * K + kbase + kk * 4);
        }
    };

    // prologue: stages 0..2
    load_stage(0); asm volatile("cp.async.commit_group;");
    load_stage(1); asm volatile("cp.async.commit_group;");
    load_stage(2); asm volatile("cp.async.commit_group;");

    for (int kt = 0; kt < KT; kt++) {
        asm volatile("cp.async.wait_group 2;");
        __syncthreads();

        int s = kt & (NSTG - 1);
        uint32_t sA = sb + s * STAGE;
        uint32_t sB = sA + HALF;

        #pragma unroll
        for (int k8 = 0; k8 < 4; k8++) {
            uint32_t a[4][4], b[4][2];
            #pragma unroll
            for (int mt = 0; mt < 4; mt++)
                ldsm_x4(a[mt], sA + a_off + (uint32_t)mt * (16 * ROWB) + k8 * 32);
            #pragma unroll
            for (int nt = 0; nt < 4; nt++)
                ldsm_x2(b[nt], sB + b_off + (uint32_t)nt * (8 * ROWB) + k8 * 32);
            #pragma unroll
            for (int mt = 0; mt < 4; mt++)
                #pragma unroll
                for (int nt = 0; nt < 4; nt++)
                    mma_tf32(acc[mt][nt], a[mt], b[nt]);
        }

        // prefetch stage kt+3 (slot (kt+3)%4 == (kt-1)%4, whose compute finished
        // before the sync above in every warp's program order)
        load_stage(kt + 3);
        asm volatile("cp.async.commit_group;");
    }

    // ---------------- epilogue ----------------
    const int rbase = m0 + warp_m + (lane >> 2);
    const int cbase = n0 + warp_n + 2 * (lane & 3);
    #pragma unroll
    for (int mt = 0; mt < 4; mt++) {
        #pragma unroll
        for (int nt = 0; nt < 4; nt++) {
            int col = cbase + nt * 8;
            float2 bi = *(const float2*)(bias + col);
            #pragma unroll
            for (int half = 0; half < 2; half++) {
                int row = rbase + mt * 16 + half * 8;
                size_t ro = (size_t)row * N + col;
                float ox = acc[mt][nt][2 * half + 0] + bi.x;
                float oy = acc[mt][nt][2 * half + 1] + bi.y;
                if (do_gelu) {
                    ox = tf32r(gelu_f(ox));
                    oy = tf32r(gelu_f(oy));
                }
                if (res) {
                    float2 rv = *(const float2*)(res + ro);
                    ox += rv.x; oy += rv.y;
                }
                *(float2*)(C + ro) = make_float2(ox, oy);
            }
        }
    }
}

// ---------------- LayerNorm: one block per row, D=1024, 256 thr ----------
__global__ __launch_bounds__(256) void ln_kernel(
    const float* __restrict__ x, const float* __restrict__ g,
    const float* __restrict__ b, float* __restrict__ out, int round_tf32)
{
    int row = blockIdx.x;
    int t = threadIdx.x;
    const float4* xr = (const float4*)(x + (size_t)row * D_);
    float4 v = xr[t];

    __shared__ float red[8];
    float s = v.x + v.y + v.z + v.w;
    #pragma unroll
    for (int o = 16; o; o >>= 1) s += __shfl_xor_sync(0xffffffffu, s, o);
    if ((t & 31) == 0) red[t >> 5] = s;
    __syncthreads();
    float tot = red[0];
    #pragma unroll
    for (int w = 1; w < 8; w++) tot += red[w];
    float mu = tot * (1.0f / D_);
    float dx = v.x - mu, dy = v.y - mu, dz = v.z - mu, dw = v.w - mu;
    __syncthreads();
    float s2 = dx*dx + dy*dy + dz*dz + dw*dw;
    #pragma unroll
    for (int o = 16; o; o >>= 1) s2 += __shfl_xor_sync(0xffffffffu, s2, o);
    if ((t & 31) == 0) red[t >> 5] = s2;
    __syncthreads();
    float tot2 = red[0];
    #pragma unroll
    for (int w = 1; w < 8; w++) tot2 += red[w];
    float rstd = rsqrtf(tot2 * (1.0f / D_) + 1e-5f);

    float4 gv = ((const float4*)g)[t];
    float4 bv = ((const float4*)b)[t];
    float4 o4;
    o4.x = dx * rstd * gv.x + bv.x;
    o4.y = dy * rstd * gv.y + bv.y;
    o4.z = dz * rstd * gv.z + bv.z;
    o4.w = dw * rstd * gv.w + bv.w;
    if (round_tf32) {
        o4.x = tf32r(o4.x); o4.y = tf32r(o4.y);
        o4.z = tf32r(o4.z); o4.w = tf32r(o4.w);
    }
    ((float4*)(out + (size_t)row * D_))[t] = o4;
}

// ---------------- tree-relative attention: one warp per (b,h,l) ----------
// q/k/v live packed in qkv[row][3*D]: q at +0, k at +D, v at +2D
__global__ __launch_bounds__(256) void attn_kernel(
    const float* __restrict__ qkv, const int* __restrict__ pos,
    const float* __restrict__ rq, const float* __restrict__ rk,
    const float* __restrict__ rv, float* __restrict__ ctx)
{
    int gw   = blockIdx.x * (blockDim.x >> 5) + (threadIdx.x >> 5);
    int lane = threadIdx.x & 31;
    int l  = gw & (L_ - 1);
    int bh = gw >> 10;
    int h  = bh & (H_ - 1);
    int b  = bh >> 4;

    size_t qoff = (size_t)(b * L_ + l) * QSTR + h * DK_ + lane * 2;
    float2 qv = *(const float2*)(qkv + qoff);
    const int* pp = pos + ((size_t)(b * H_ + h) * R_) * L_ + l;
    const float* kb = qkv + D_  + (size_t)h * DK_ + lane * 2;
    const float* vb = qkv + 2*D_ + (size_t)h * DK_ + lane * 2;

    float sc[R_];
    int   idxs[R_];
    #pragma unroll
    for (int r = 0; r < R_; r++) {
        int idx = pp[(size_t)r * L_];
        idxs[r] = idx;
        float2 rqv = *(const float2*)(rq + (h * R_ + r) * DK_ + lane * 2);
        float2 rkv = *(const float2*)(rk + (h * R_ + r) * DK_ + lane * 2);
        float2 kg  = *(const float2*)(kb + (size_t)(b * L_ + idx) * QSTR);
        float p = (qv.x + rqv.x) * kg.x + (qv.y + rqv.y) * kg.y
                +  qv.x * rkv.x + qv.y * rkv.y;
        #pragma unroll
        for (int o = 16; o; o >>= 1) p += __shfl_xor_sync(0xffffffffu, p, o);
        sc[r] = (idx != l) ? p * 0.125f : -1e9f;
    }

    float m = sc[0];
    #pragma unroll
    for (int r = 1; r < R_; r++) m = fmaxf(m, sc[r]);
    float s = 0.0f;
    #pragma unroll
    for (int r = 0; r < R_; r++) { sc[r] = __expf(sc[r] - m); s += sc[r]; }
    float inv = 1.0f / s;

    float ax = 0.0f, ay = 0.0f;
    #pragma unroll
    for (int r = 0; r < R_; r++) {
        float a = sc[r] * inv;
        float2 rvv = *(const float2*)(rv + (h * R_ + r) * DK_ + lane * 2);
        float2 vg  = *(const float2*)(vb + (size_t)(b * L_ + idxs[r]) * QSTR);
        ax = fmaf(a, vg.x + rvv.x, ax);
        ay = fmaf(a, vg.y + rvv.y, ay);
    }
    size_t coff = (size_t)(b * L_ + l) * D_ + h * DK_ + lane * 2;
    *(float2*)(ctx + coff) = make_float2(tf32r(ax), tf32r(ay));
}

// ---------------- host orchestration -------------------------------------
extern "C" void kernel_launch(void* const* d_in, const int* in_sizes, int n_in,
                              void* d_out, int out_size)
{
    const float* emb    = (const float*)d_in[0];
    const int*   pos    = (const int*)  d_in[1];
    const float* rel_q  = (const float*)d_in[2];
    const float* rel_k  = (const float*)d_in[3];
    const float* rel_v  = (const float*)d_in[4];
    const float* attn_w = (const float*)d_in[5];
    const float* attn_b = (const float*)d_in[6];
    const float* ff_w1  = (const float*)d_in[7];
    const float* ff_b1  = (const float*)d_in[8];
    const float* ff_w2  = (const float*)d_in[9];
    const float* ff_b2  = (const float*)d_in[10];
    const float* ln_g   = (const float*)d_in[11];
    const float* ln_b   = (const float*)d_in[12];
    const float* fin_g  = (const float*)d_in[13];
    const float* fin_b  = (const float*)d_in[14];
    float* out = (float*)d_out;

    float *x, *h, *qkv, *ctx, *ff, *wta, *wtf1, *wtf2;
    cudaGetSymbolAddress((void**)&x,    g_x);
    cudaGetSymbolAddress((void**)&h,    g_h);
    cudaGetSymbolAddress((void**)&qkv,  g_qkv);
    cudaGetSymbolAddress((void**)&ctx,  g_ctx);
    cudaGetSymbolAddress((void**)&ff,   g_ff);
    cudaGetSymbolAddress((void**)&wta,  g_wt_attn);
    cudaGetSymbolAddress((void**)&wtf1, g_wt_ff1);
    cudaGetSymbolAddress((void**)&wtf2, g_wt_ff2);

    static bool attr_done = false;
    if (!attr_done) {
        cudaFuncSetAttribute(tc_gemm, cudaFuncAttributeMaxDynamicSharedMemorySize, GEMM_SMEM);
        attr_done = true;
    }

    // ---- weight transposes (tf32-rounded): W[K][N] -> Wt[N][K] ----
    transpose_k<<<dim3(D_/32, D_/32, NL_*4), dim3(32,8)>>>(attn_w, wta,  D_, D_);
    transpose_k<<<dim3(F_/32, D_/32, NL_),   dim3(32,8)>>>(ff_w1,  wtf1, D_, F_);
    transpose_k<<<dim3(D_/32, F_/32, NL_),   dim3(32,8)>>>(ff_w2,  wtf2, F_, D_);

    dim3 gQKV(3*D_/128, ROWS_/128);   // (24, 16)
    dim3 gD(D_/128, ROWS_/128);       // (8, 16)
    dim3 gF(F_/128, ROWS_/128);       // (32, 16)
    int attn_blocks = (B_ * H_ * L_) / 8;

    for (int i = 0; i < NL_; i++) {
        const float* xin = (i == 0) ? emb : x;
        const float* Wt = wta + (size_t)i * 4 * D_ * D_;   // q,k,v rows contiguous
        const float* Bb = attn_b + (size_t)i * 4 * D_;

        ln_kernel<<<ROWS_, 256>>>(xin, ln_g + (size_t)(i*2) * D_, ln_b + (size_t)(i*2) * D_, h, 1);

        // fused QKV: N = 3072 (weights/biases for j=0..2 are contiguous)
        tc_gemm<<<gQKV, 256, GEMM_SMEM>>>(h, Wt, Bb, nullptr, qkv, ROWS_, QSTR, D_, 0);

        attn_kernel<<<attn_blocks, 256>>>(qkv, pos, rel_q, rel_k, rel_v, ctx);

        tc_gemm<<<gD, 256, GEMM_SMEM>>>(ctx, Wt + (size_t)3*D_*D_, Bb + 3*D_, xin, x, ROWS_, D_, D_, 0);

        ln_kernel<<<ROWS_, 256>>>(x, ln_g + (size_t)(i*2+1) * D_, ln_b + (size_t)(i*2+1) * D_, h, 1);

        tc_gemm<<<gF, 256, GEMM_SMEM>>>(h,  wtf1 + (size_t)i * D_ * F_, ff_b1 + (size_t)i * F_,
                                        nullptr, ff, ROWS_, F_, D_, 1);
        tc_gemm<<<gD, 256, GEMM_SMEM>>>(ff, wtf2 + (size_t)i * F_ * D_, ff_b2 + (size_t)i * D_,
                                        x, x, ROWS_, D_, F_, 0);
    }
    ln_kernel<<<ROWS_, 256>>>(x, fin_g, fin_b, out, 0);
}

// round 6
// speedup vs baseline: 6.9530x; 1.5788x over previous
#include <cuda_runtime.h>
#include <cuda_fp16.h>
#include <math.h>
#include <stdint.h>

#define B_  2
#define L_  1024
#define D_  1024
#define H_  16
#define R_  16
#define DK_ 64
#define F_  4096
#define NL_ 4
#define ROWS_ (B_*L_)
#define QSTR (3*D_)

// ---------------- scratch (no runtime allocation allowed) ----------------
__device__ float  g_x  [ROWS_*D_];
__device__ __half g_h  [ROWS_*D_];
__device__ __half g_qkv[ROWS_*3*D_];
__device__ __half g_ctx[ROWS_*D_];
__device__ __half g_ff [ROWS_*F_];
__device__ __half g_wt_attn[(size_t)NL_*4*D_*D_];
__device__ __half g_wt_ff1 [(size_t)NL_*D_*F_];
__device__ __half g_wt_ff2 [(size_t)NL_*F_*D_];

// ---------------- helpers -------------------------------------------------
__device__ __forceinline__ uint32_t smem_to_u32(const void* p) {
    uint32_t a;
    asm("{ .reg .u64 t; cvta.to.shared.u64 t, %1; cvt.u32.u64 %0, t; }" : "=r"(a) : "l"(p));
    return a;
}
__device__ __forceinline__ void cp16(uint32_t dst, const void* src) {
    asm volatile("cp.async.cg.shared.global [%0], [%1], 16;" :: "r"(dst), "l"(src));
}
__device__ __forceinline__ void ldsm_x4(uint32_t* r, uint32_t addr) {
    asm volatile("ldmatrix.sync.aligned.m8n8.x4.shared.b16 {%0,%1,%2,%3}, [%4];"
        : "=r"(r[0]), "=r"(r[1]), "=r"(r[2]), "=r"(r[3]) : "r"(addr));
}
__device__ __forceinline__ void ldsm_x2(uint32_t* r, uint32_t addr) {
    asm volatile("ldmatrix.sync.aligned.m8n8.x2.shared.b16 {%0,%1}, [%2];"
        : "=r"(r[0]), "=r"(r[1]) : "r"(addr));
}
__device__ __forceinline__ void mma_f16(float* c, const uint32_t* a, const uint32_t* b) {
    asm volatile(
        "mma.sync.aligned.m16n8k16.row.col.f32.f16.f16.f32 "
        "{%0,%1,%2,%3}, {%4,%5,%6,%7}, {%8,%9}, {%0,%1,%2,%3};"
        : "+f"(c[0]), "+f"(c[1]), "+f"(c[2]), "+f"(c[3])
        : "r"(a[0]), "r"(a[1]), "r"(a[2]), "r"(a[3]), "r"(b[0]), "r"(b[1]));
}
__device__ __forceinline__ float gelu_f(float x) {
    float x3 = x * x * x;
    return 0.5f * x * (1.0f + tanhf(0.7978845608028654f * (x + 0.044715f * x3)));
}

// ---------------- weight transpose (src [K][N] f32 -> dst [N][K] f16) ------
__global__ __launch_bounds__(256) void transpose_k(
    const float* __restrict__ src, __half* __restrict__ dst, int K, int N)
{
    __shared__ float t[32][33];
    src += (size_t)blockIdx.z * K * N;
    dst += (size_t)blockIdx.z * K * N;
    int n0 = blockIdx.x * 32, k0 = blockIdx.y * 32;
    int tx = threadIdx.x, ty = threadIdx.y;
    #pragma unroll
    for (int i = 0; i < 32; i += 8)
        t[ty + i][tx] = src[(size_t)(k0 + ty + i) * N + n0 + tx];
    __syncthreads();
    #pragma unroll
    for (int i = 0; i < 32; i += 8)
        dst[(size_t)(n0 + ty + i) * K + k0 + tx] = __float2half_rn(t[tx][ty + i]);
}

// ---------------- fp16 mma.sync GEMM: C[M,N] = A[M,K] * Bt[N,K]^T ----------
// CTA 128x128, 8 warps (warp tile 64x32), BK=64 fp16 elems, 4-stage cp.async.
#define BKG   64             // K elements per stage (128 bytes fp16)
#define ROWB  144            // bytes per smem row (128B data + 16B pad)
#define HALF_ (128*ROWB)     // 18432 bytes (A or B tile)
#define STAGE (2*HALF_)      // 36864
#define NSTG  4
#define GEMM_SMEM (NSTG*STAGE)   // 147456

__global__ __launch_bounds__(256, 1) void tc_gemm(
    const __half* __restrict__ A, const __half* __restrict__ Bt,
    const float* __restrict__ bias, const float* __restrict__ res,
    void* __restrict__ Cp, int M, int N, int K, int do_gelu, int out_half)
{
    extern __shared__ char smem[];
    const uint32_t sb = smem_to_u32(smem);
    const int tid  = threadIdx.x;
    const int wid  = tid >> 5;
    const int lane = tid & 31;

    const int m0 = blockIdx.y * 128;
    const int n0 = blockIdx.x * 128;
    const int KT = K / BKG;

    const int warp_m = (wid >> 2) * 64;      // 0 or 64
    const int warp_n = (wid & 3) * 32;       // 0,32,64,96

    // A m16k16 fragment: lanes 0-15 -> rows (k-seg 0), lanes 16-31 -> same rows, k-seg 1
    const uint32_t a_off = (uint32_t)(warp_m + (lane & 15)) * ROWB
                         + (uint32_t)(lane >> 4) * 16;
    // B n8k16 fragment: lanes 0-7 -> n rows seg0, lanes 8-15 -> seg1 (x2 uses lanes 0-15)
    const uint32_t b_off = (uint32_t)(warp_n + (lane & 7)) * ROWB
                         + (uint32_t)((lane >> 3) & 1) * 16;

    float acc[4][4][4];
    #pragma unroll
    for (int i = 0; i < 4; i++)
        #pragma unroll
        for (int j = 0; j < 4; j++)
            #pragma unroll
            for (int v = 0; v < 4; v++) acc[i][j][v] = 0.0f;

    // --- stage loader: 4 A-chunks + 4 B-chunks of 16B (8 fp16) per thread ---
    auto load_stage = [&](int kt) {
        if (kt >= KT) return;
        int s = kt & (NSTG - 1);
        uint32_t dA = sb + s * STAGE;
        uint32_t dB = dA + HALF_;
        int kbase = kt * BKG;
        #pragma unroll
        for (int i = 0; i < 4; i++) {
            int c = tid + i * 256;             // 0..1023
            int row = c >> 3, kk = c & 7;
            cp16(dA + row * ROWB + kk * 16,
                 A + (size_t)(m0 + row) * K + kbase + kk * 8);
        }
        #pragma unroll
        for (int i = 0; i < 4; i++) {
            int c = tid + i * 256;
            int row = c >> 3, kk = c & 7;
            cp16(dB + row * ROWB + kk * 16,
                 Bt + (size_t)(n0 + row) * K + kbase + kk * 8);
        }
    };

    load_stage(0); asm volatile("cp.async.commit_group;");
    load_stage(1); asm volatile("cp.async.commit_group;");
    load_stage(2); asm volatile("cp.async.commit_group;");

    for (int kt = 0; kt < KT; kt++) {
        asm volatile("cp.async.wait_group 2;");
        __syncthreads();

        int s = kt & (NSTG - 1);
        uint32_t sA = sb + s * STAGE;
        uint32_t sB = sA + HALF_;

        #pragma unroll
        for (int ks = 0; ks < 4; ks++) {       // 4 x k16 steps = BK 64
            uint32_t a[4][4], b[4][2];
            #pragma unroll
            for (int mt = 0; mt < 4; mt++)
                ldsm_x4(a[mt], sA + a_off + (uint32_t)mt * (16 * ROWB) + ks * 32);
            #pragma unroll
            for (int nt = 0; nt < 4; nt++)
                ldsm_x2(b[nt], sB + b_off + (uint32_t)nt * (8 * ROWB) + ks * 32);
            #pragma unroll
            for (int mt = 0; mt < 4; mt++)
                #pragma unroll
                for (int nt = 0; nt < 4; nt++)
                    mma_f16(acc[mt][nt], a[mt], b[nt]);
        }

        load_stage(kt + 3);
        asm volatile("cp.async.commit_group;");
    }

    // ---------------- epilogue ----------------
    const int rbase = m0 + warp_m + (lane >> 2);
    const int cbase = n0 + warp_n + 2 * (lane & 3);
    #pragma unroll
    for (int mt = 0; mt < 4; mt++) {
        #pragma unroll
        for (int nt = 0; nt < 4; nt++) {
            int col = cbase + nt * 8;
            float2 bi = *(const float2*)(bias + col);
            #pragma unroll
            for (int half = 0; half < 2; half++) {
                int row = rbase + mt * 16 + half * 8;
                size_t ro = (size_t)row * N + col;
                float ox = acc[mt][nt][2 * half + 0] + bi.x;
                float oy = acc[mt][nt][2 * half + 1] + bi.y;
                if (do_gelu) { ox = gelu_f(ox); oy = gelu_f(oy); }
                if (res) {
                    float2 rv = *(const float2*)(res + ro);
                    ox += rv.x; oy += rv.y;
                }
                if (out_half) {
                    *(__half2*)((__half*)Cp + ro) = __floats2half2_rn(ox, oy);
                } else {
                    *(float2*)((float*)Cp + ro) = make_float2(ox, oy);
                }
            }
        }
    }
}

// ---------------- LayerNorm: one block per row, D=1024, 256 thr ----------
// out_half=1 -> writes __half (feeds GEMM); else fp32
__global__ __launch_bounds__(256) void ln_kernel(
    const float* __restrict__ x, const float* __restrict__ g,
    const float* __restrict__ b, void* __restrict__ out, int out_half)
{
    int row = blockIdx.x;
    int t = threadIdx.x;
    const float4* xr = (const float4*)(x + (size_t)row * D_);
    float4 v = xr[t];

    __shared__ float red[8];
    float s = v.x + v.y + v.z + v.w;
    #pragma unroll
    for (int o = 16; o; o >>= 1) s += __shfl_xor_sync(0xffffffffu, s, o);
    if ((t & 31) == 0) red[t >> 5] = s;
    __syncthreads();
    float tot = red[0];
    #pragma unroll
    for (int w = 1; w < 8; w++) tot += red[w];
    float mu = tot * (1.0f / D_);
    float dx = v.x - mu, dy = v.y - mu, dz = v.z - mu, dw = v.w - mu;
    __syncthreads();
    float s2 = dx*dx + dy*dy + dz*dz + dw*dw;
    #pragma unroll
    for (int o = 16; o; o >>= 1) s2 += __shfl_xor_sync(0xffffffffu, s2, o);
    if ((t & 31) == 0) red[t >> 5] = s2;
    __syncthreads();
    float tot2 = red[0];
    #pragma unroll
    for (int w = 1; w < 8; w++) tot2 += red[w];
    float rstd = rsqrtf(tot2 * (1.0f / D_) + 1e-5f);

    float4 gv = ((const float4*)g)[t];
    float4 bv = ((const float4*)b)[t];
    float ox = dx * rstd * gv.x + bv.x;
    float oy = dy * rstd * gv.y + bv.y;
    float oz = dz * rstd * gv.z + bv.z;
    float ow = dw * rstd * gv.w + bv.w;
    if (out_half) {
        __half2* po = (__half2*)((__half*)out + (size_t)row * D_) + t * 2;
        po[0] = __floats2half2_rn(ox, oy);
        po[1] = __floats2half2_rn(oz, ow);
    } else {
        ((float4*)((float*)out + (size_t)row * D_))[t] = make_float4(ox, oy, oz, ow);
    }
}

// ---------------- tree-relative attention: one warp per (b,h,l) ----------
// q/k/v packed fp16 in qkv[row][3*D]: q at +0, k at +D, v at +2D; ctx fp16
__global__ __launch_bounds__(256) void attn_kernel(
    const __half* __restrict__ qkv, const int* __restrict__ pos,
    const float* __restrict__ rq, const float* __restrict__ rk,
    const float* __restrict__ rv, __half* __restrict__ ctx)
{
    int gw   = blockIdx.x * (blockDim.x >> 5) + (threadIdx.x >> 5);
    int lane = threadIdx.x & 31;
    int l  = gw & (L_ - 1);
    int bh = gw >> 10;
    int h  = bh & (H_ - 1);
    int b  = bh >> 4;

    size_t qoff = (size_t)(b * L_ + l) * QSTR + h * DK_ + lane * 2;
    float2 qv = __half22float2(*(const __half2*)(qkv + qoff));
    const int* pp = pos + ((size_t)(b * H_ + h) * R_) * L_ + l;
    const __half* kb = qkv + D_   + (size_t)h * DK_ + lane * 2;
    const __half* vb = qkv + 2*D_ + (size_t)h * DK_ + lane * 2;

    float sc[R_];
    int   idxs[R_];
    #pragma unroll
    for (int r = 0; r < R_; r++) {
        int idx = pp[(size_t)r * L_];
        idxs[r] = idx;
        float2 rqv = *(const float2*)(rq + (h * R_ + r) * DK_ + lane * 2);
        float2 rkv = *(const float2*)(rk + (h * R_ + r) * DK_ + lane * 2);
        float2 kg  = __half22float2(*(const __half2*)(kb + (size_t)(b * L_ + idx) * QSTR));
        float p = (qv.x + rqv.x) * kg.x + (qv.y + rqv.y) * kg.y
                +  qv.x * rkv.x + qv.y * rkv.y;
        #pragma unroll
        for (int o = 16; o; o >>= 1) p += __shfl_xor_sync(0xffffffffu, p, o);
        sc[r] = (idx != l) ? p * 0.125f : -1e9f;
    }

    float m = sc[0];
    #pragma unroll
    for (int r = 1; r < R_; r++) m = fmaxf(m, sc[r]);
    float s = 0.0f;
    #pragma unroll
    for (int r = 0; r < R_; r++) { sc[r] = __expf(sc[r] - m); s += sc[r]; }
    float inv = 1.0f / s;

    float ax = 0.0f, ay = 0.0f;
    #pragma unroll
    for (int r = 0; r < R_; r++) {
        float a = sc[r] * inv;
        float2 rvv = *(const float2*)(rv + (h * R_ + r) * DK_ + lane * 2);
        float2 vg  = __half22float2(*(const __half2*)(vb + (size_t)(b * L_ + idxs[r]) * QSTR));
        ax = fmaf(a, vg.x + rvv.x, ax);
        ay = fmaf(a, vg.y + rvv.y, ay);
    }
    size_t coff = (size_t)(b * L_ + l) * D_ + h * DK_ + lane * 2;
    *(__half2*)(ctx + coff) = __floats2half2_rn(ax, ay);
}

// ---------------- host orchestration -------------------------------------
extern "C" void kernel_launch(void* const* d_in, const int* in_sizes, int n_in,
                              void* d_out, int out_size)
{
    const float* emb    = (const float*)d_in[0];
    const int*   pos    = (const int*)  d_in[1];
    const float* rel_q  = (const float*)d_in[2];
    const float* rel_k  = (const float*)d_in[3];
    const float* rel_v  = (const float*)d_in[4];
    const float* attn_w = (const float*)d_in[5];
    const float* attn_b = (const float*)d_in[6];
    const float* ff_w1  = (const float*)d_in[7];
    const float* ff_b1  = (const float*)d_in[8];
    const float* ff_w2  = (const float*)d_in[9];
    const float* ff_b2  = (const float*)d_in[10];
    const float* ln_g   = (const float*)d_in[11];
    const float* ln_b   = (const float*)d_in[12];
    const float* fin_g  = (const float*)d_in[13];
    const float* fin_b  = (const float*)d_in[14];
    float* out = (float*)d_out;

    float *x;
    __half *h, *qkv, *ctx, *ff, *wta, *wtf1, *wtf2;
    cudaGetSymbolAddress((void**)&x,    g_x);
    cudaGetSymbolAddress((void**)&h,    g_h);
    cudaGetSymbolAddress((void**)&qkv,  g_qkv);
    cudaGetSymbolAddress((void**)&ctx,  g_ctx);
    cudaGetSymbolAddress((void**)&ff,   g_ff);
    cudaGetSymbolAddress((void**)&wta,  g_wt_attn);
    cudaGetSymbolAddress((void**)&wtf1, g_wt_ff1);
    cudaGetSymbolAddress((void**)&wtf2, g_wt_ff2);

    static bool attr_done = false;
    if (!attr_done) {
        cudaFuncSetAttribute(tc_gemm, cudaFuncAttributeMaxDynamicSharedMemorySize, GEMM_SMEM);
        attr_done = true;
    }

    // ---- weight transposes: W[K][N] f32 -> Wt[N][K] f16 ----
    transpose_k<<<dim3(D_/32, D_/32, NL_*4), dim3(32,8)>>>(attn_w, wta,  D_, D_);
    transpose_k<<<dim3(F_/32, D_/32, NL_),   dim3(32,8)>>>(ff_w1,  wtf1, D_, F_);
    transpose_k<<<dim3(D_/32, F_/32, NL_),   dim3(32,8)>>>(ff_w2,  wtf2, F_, D_);

    dim3 gQKV(3*D_/128, ROWS_/128);   // (24, 16)
    dim3 gD(D_/128, ROWS_/128);       // (8, 16)
    dim3 gF(F_/128, ROWS_/128);       // (32, 16)
    int attn_blocks = (B_ * H_ * L_) / 8;

    for (int i = 0; i < NL_; i++) {
        const float* xin = (i == 0) ? emb : x;
        const __half* Wt = wta + (size_t)i * 4 * D_ * D_;   // q,k,v rows contiguous
        const float* Bb = attn_b + (size_t)i * 4 * D_;

        ln_kernel<<<ROWS_, 256>>>(xin, ln_g + (size_t)(i*2) * D_, ln_b + (size_t)(i*2) * D_, h, 1);

        // fused QKV: N = 3072, fp16 out
        tc_gemm<<<gQKV, 256, GEMM_SMEM>>>(h, Wt, Bb, nullptr, qkv, ROWS_, QSTR, D_, 0, 1);

        attn_kernel<<<attn_blocks, 256>>>(qkv, pos, rel_q, rel_k, rel_v, ctx);

        // O-proj + residual, fp32 out
        tc_gemm<<<gD, 256, GEMM_SMEM>>>(ctx, Wt + (size_t)3*D_*D_, Bb + 3*D_, xin, x, ROWS_, D_, D_, 0, 0);

        ln_kernel<<<ROWS_, 256>>>(x, ln_g + (size_t)(i*2+1) * D_, ln_b + (size_t)(i*2+1) * D_, h, 1);

        // FF1 + gelu, fp16 out
        tc_gemm<<<gF, 256, GEMM_SMEM>>>(h,  wtf1 + (size_t)i * D_ * F_, ff_b1 + (size_t)i * F_,
                                        nullptr, ff, ROWS_, F_, D_, 1, 1);
        // FF2 + residual, fp32 out
        tc_gemm<<<gD, 256, GEMM_SMEM>>>(ff, wtf2 + (size_t)i * F_ * D_, ff_b2 + (size_t)i * D_,
                                        x, x, ROWS_, D_, F_, 0, 0);
    }
    ln_kernel<<<ROWS_, 256>>>(x, fin_g, fin_b, out, 0);
}

// round 7
// speedup vs baseline: 7.5654x; 1.0881x over previous
#include <cuda_runtime.h>
#include <cuda_fp16.h>
#include <math.h>
#include <stdint.h>

#define B_  2
#define L_  1024
#define D_  1024
#define H_  16
#define R_  16
#define DK_ 64
#define F_  4096
#define NL_ 4
#define ROWS_ (B_*L_)
#define QSTR (3*D_)

// ---------------- scratch (no runtime allocation allowed) ----------------
__device__ float  g_x  [ROWS_*D_];
__device__ __half g_h  [ROWS_*D_];
__device__ __half g_qkv[ROWS_*3*D_];
__device__ __half g_ctx[ROWS_*D_];
__device__ __half g_ff [ROWS_*F_];
__device__ __half g_wt_attn[(size_t)NL_*4*D_*D_];
__device__ __half g_wt_ff1 [(size_t)NL_*D_*F_];
__device__ __half g_wt_ff2 [(size_t)NL_*F_*D_];

// ---------------- helpers -------------------------------------------------
__device__ __forceinline__ uint32_t smem_to_u32(const void* p) {
    uint32_t a;
    asm("{ .reg .u64 t; cvta.to.shared.u64 t, %1; cvt.u32.u64 %0, t; }" : "=r"(a) : "l"(p));
    return a;
}
__device__ __forceinline__ void cp16(uint32_t dst, const void* src) {
    asm volatile("cp.async.cg.shared.global [%0], [%1], 16;" :: "r"(dst), "l"(src));
}
__device__ __forceinline__ void ldsm_x4(uint32_t* r, uint32_t addr) {
    asm volatile("ldmatrix.sync.aligned.m8n8.x4.shared.b16 {%0,%1,%2,%3}, [%4];"
        : "=r"(r[0]), "=r"(r[1]), "=r"(r[2]), "=r"(r[3]) : "r"(addr));
}
__device__ __forceinline__ void mma_f16(float* c, const uint32_t* a, const uint32_t* b) {
    asm volatile(
        "mma.sync.aligned.m16n8k16.row.col.f32.f16.f16.f32 "
        "{%0,%1,%2,%3}, {%4,%5,%6,%7}, {%8,%9}, {%0,%1,%2,%3};"
        : "+f"(c[0]), "+f"(c[1]), "+f"(c[2]), "+f"(c[3])
        : "r"(a[0]), "r"(a[1]), "r"(a[2]), "r"(a[3]), "r"(b[0]), "r"(b[1]));
}
__device__ __forceinline__ float gelu_f(float x) {
    float x3 = x * x * x;
    return 0.5f * x * (1.0f + tanhf(0.7978845608028654f * (x + 0.044715f * x3)));
}

// ---------------- weight transpose (src [K][N] f32 -> dst [N][K] f16) ------
__global__ __launch_bounds__(256) void transpose_k(
    const float* __restrict__ src, __half* __restrict__ dst, int K, int N)
{
    __shared__ float t[32][33];
    src += (size_t)blockIdx.z * K * N;
    dst += (size_t)blockIdx.z * K * N;
    int n0 = blockIdx.x * 32, k0 = blockIdx.y * 32;
    int tx = threadIdx.x, ty = threadIdx.y;
    #pragma unroll
    for (int i = 0; i < 32; i += 8)
        t[ty + i][tx] = src[(size_t)(k0 + ty + i) * N + n0 + tx];
    __syncthreads();
    #pragma unroll
    for (int i = 0; i < 32; i += 8)
        dst[(size_t)(n0 + ty + i) * K + k0 + tx] = __float2half_rn(t[tx][ty + i]);
}

// ---------------- fp16 mma.sync GEMM: C[M,N] = A[M,K] * Bt[N,K]^T ----------
// CTA 128x128, 8 warps (warp tile 64x32), BK=64 fp16, 3-stage cp.async,
// 2 CTAs/SM (110.6KB smem each).
#define BKG   64             // K elements per stage (128 bytes fp16)
#define ROWB  144            // bytes per smem row (128B data + 16B pad)
#define HALF_ (128*ROWB)     // 18432 bytes (A or B tile)
#define STAGE (2*HALF_)      // 36864
#define NSTG  3
#define GEMM_SMEM (NSTG*STAGE)   // 110592

__global__ __launch_bounds__(256, 2) void tc_gemm(
    const __half* __restrict__ A, const __half* __restrict__ Bt,
    const float* __restrict__ bias, const float* __restrict__ res,
    void* __restrict__ Cp, int M, int N, int K, int do_gelu, int out_half)
{
    extern __shared__ char smem[];
    const uint32_t sb = smem_to_u32(smem);
    const int tid  = threadIdx.x;
    const int wid  = tid >> 5;
    const int lane = tid & 31;

    const int m0 = blockIdx.y * 128;
    const int n0 = blockIdx.x * 128;
    const int KT = K / BKG;

    const int warp_m = (wid >> 2) * 64;      // 0 or 64
    const int warp_n = (wid & 3) * 32;       // 0,32,64,96

    // A m16k16 x4: lanes 0-15 -> rows, lanes 16-31 -> +16B k-seg
    const uint32_t a_off = (uint32_t)(warp_m + (lane & 15)) * ROWB
                         + (uint32_t)(lane >> 4) * 16;
    // B x4 (two n8 frags): lanes0-7 rows+seg0, 8-15 rows+seg1, 16-23 rows+8 seg0, 24-31 rows+8 seg1
    const uint32_t b_off = (uint32_t)(warp_n + (lane & 7) + ((lane >> 4) << 3)) * ROWB
                         + (uint32_t)((lane >> 3) & 1) * 16;

    float acc[4][4][4];
    #pragma unroll
    for (int i = 0; i < 4; i++)
        #pragma unroll
        for (int j = 0; j < 4; j++)
            #pragma unroll
            for (int v = 0; v < 4; v++) acc[i][j][v] = 0.0f;

    // --- stage loader: 4 A-chunks + 4 B-chunks of 16B (8 fp16) per thread ---
    auto load_stage = [&](int kt) {
        if (kt >= KT) return;
        int s = kt % NSTG;
        uint32_t dA = sb + s * STAGE;
        uint32_t dB = dA + HALF_;
        int kbase = kt * BKG;
        #pragma unroll
        for (int i = 0; i < 4; i++) {
            int c = tid + i * 256;             // 0..1023
            int row = c >> 3, kk = c & 7;
            cp16(dA + row * ROWB + kk * 16,
                 A + (size_t)(m0 + row) * K + kbase + kk * 8);
        }
        #pragma unroll
        for (int i = 0; i < 4; i++) {
            int c = tid + i * 256;
            int row = c >> 3, kk = c & 7;
            cp16(dB + row * ROWB + kk * 16,
                 Bt + (size_t)(n0 + row) * K + kbase + kk * 8);
        }
    };

    load_stage(0); asm volatile("cp.async.commit_group;");
    load_stage(1); asm volatile("cp.async.commit_group;");

    for (int kt = 0; kt < KT; kt++) {
        asm volatile("cp.async.wait_group 1;");
        __syncthreads();

        int s = kt % NSTG;
        uint32_t sA = sb + s * STAGE;
        uint32_t sB = sA + HALF_;

        #pragma unroll
        for (int ks = 0; ks < 4; ks++) {       // 4 x k16 steps = BK 64
            uint32_t a[4][4], b[4][2];
            #pragma unroll
            for (int mt = 0; mt < 4; mt++)
                ldsm_x4(a[mt], sA + a_off + (uint32_t)mt * (16 * ROWB) + ks * 32);
            #pragma unroll
            for (int g = 0; g < 2; g++) {
                uint32_t t4[4];
                ldsm_x4(t4, sB + b_off + (uint32_t)g * (16 * ROWB) + ks * 32);
                b[2*g][0] = t4[0]; b[2*g][1] = t4[1];
                b[2*g+1][0] = t4[2]; b[2*g+1][1] = t4[3];
            }
            #pragma unroll
            for (int mt = 0; mt < 4; mt++)
                #pragma unroll
                for (int nt = 0; nt < 4; nt++)
                    mma_f16(acc[mt][nt], a[mt], b[nt]);
        }

        // prefetch stage kt+2 -> slot (kt+2)%3 == (kt-1)%3, consumed before the
        // sync above in every warp's program order
        load_stage(kt + 2);
        asm volatile("cp.async.commit_group;");
    }

    // ---------------- epilogue ----------------
    const int rbase = m0 + warp_m + (lane >> 2);
    const int cbase = n0 + warp_n + 2 * (lane & 3);
    #pragma unroll
    for (int mt = 0; mt < 4; mt++) {
        #pragma unroll
        for (int nt = 0; nt < 4; nt++) {
            int col = cbase + nt * 8;
            float2 bi = *(const float2*)(bias + col);
            #pragma unroll
            for (int half = 0; half < 2; half++) {
                int row = rbase + mt * 16 + half * 8;
                size_t ro = (size_t)row * N + col;
                float ox = acc[mt][nt][2 * half + 0] + bi.x;
                float oy = acc[mt][nt][2 * half + 1] + bi.y;
                if (do_gelu) { ox = gelu_f(ox); oy = gelu_f(oy); }
                if (res) {
                    float2 rv = *(const float2*)(res + ro);
                    ox += rv.x; oy += rv.y;
                }
                if (out_half) {
                    *(__half2*)((__half*)Cp + ro) = __floats2half2_rn(ox, oy);
                } else {
                    *(float2*)((float*)Cp + ro) = make_float2(ox, oy);
                }
            }
        }
    }
}

// ---------------- LayerNorm: one block per row, D=1024, 256 thr ----------
__global__ __launch_bounds__(256) void ln_kernel(
    const float* __restrict__ x, const float* __restrict__ g,
    const float* __restrict__ b, void* __restrict__ out, int out_half)
{
    int row = blockIdx.x;
    int t = threadIdx.x;
    const float4* xr = (const float4*)(x + (size_t)row * D_);
    float4 v = xr[t];

    __shared__ float red[8];
    float s = v.x + v.y + v.z + v.w;
    #pragma unroll
    for (int o = 16; o; o >>= 1) s += __shfl_xor_sync(0xffffffffu, s, o);
    if ((t & 31) == 0) red[t >> 5] = s;
    __syncthreads();
    float tot = red[0];
    #pragma unroll
    for (int w = 1; w < 8; w++) tot += red[w];
    float mu = tot * (1.0f / D_);
    float dx = v.x - mu, dy = v.y - mu, dz = v.z - mu, dw = v.w - mu;
    __syncthreads();
    float s2 = dx*dx + dy*dy + dz*dz + dw*dw;
    #pragma unroll
    for (int o = 16; o; o >>= 1) s2 += __shfl_xor_sync(0xffffffffu, s2, o);
    if ((t & 31) == 0) red[t >> 5] = s2;
    __syncthreads();
    float tot2 = red[0];
    #pragma unroll
    for (int w = 1; w < 8; w++) tot2 += red[w];
    float rstd = rsqrtf(tot2 * (1.0f / D_) + 1e-5f);

    float4 gv = ((const float4*)g)[t];
    float4 bv = ((const float4*)b)[t];
    float ox = dx * rstd * gv.x + bv.x;
    float oy = dy * rstd * gv.y + bv.y;
    float oz = dz * rstd * gv.z + bv.z;
    float ow = dw * rstd * gv.w + bv.w;
    if (out_half) {
        __half2* po = (__half2*)((__half*)out + (size_t)row * D_) + t * 2;
        po[0] = __floats2half2_rn(ox, oy);
        po[1] = __floats2half2_rn(oz, ow);
    } else {
        ((float4*)((float*)out + (size_t)row * D_))[t] = make_float4(ox, oy, oz, ow);
    }
}

// ---------------- tree-relative attention: one warp per (b,h,l) ----------
__global__ __launch_bounds__(256) void attn_kernel(
    const __half* __restrict__ qkv, const int* __restrict__ pos,
    const float* __restrict__ rq, const float* __restrict__ rk,
    const float* __restrict__ rv, __half* __restrict__ ctx)
{
    int gw   = blockIdx.x * (blockDim.x >> 5) + (threadIdx.x >> 5);
    int lane = threadIdx.x & 31;
    int l  = gw & (L_ - 1);
    int bh = gw >> 10;
    int h  = bh & (H_ - 1);
    int b  = bh >> 4;

    size_t qoff = (size_t)(b * L_ + l) * QSTR + h * DK_ + lane * 2;
    float2 qv = __half22float2(*(const __half2*)(qkv + qoff));
    const int* pp = pos + ((size_t)(b * H_ + h) * R_) * L_ + l;
    const __half* kb = qkv + D_   + (size_t)h * DK_ + lane * 2;
    const __half* vb = qkv + 2*D_ + (size_t)h * DK_ + lane * 2;

    float sc[R_];
    int   idxs[R_];
    #pragma unroll
    for (int r = 0; r < R_; r++) {
        int idx = pp[(size_t)r * L_];
        idxs[r] = idx;
        float2 rqv = *(const float2*)(rq + (h * R_ + r) * DK_ + lane * 2);
        float2 rkv = *(const float2*)(rk + (h * R_ + r) * DK_ + lane * 2);
        float2 kg  = __half22float2(*(const __half2*)(kb + (size_t)(b * L_ + idx) * QSTR));
        float p = (qv.x + rqv.x) * kg.x + (qv.y + rqv.y) * kg.y
                +  qv.x * rkv.x + qv.y * rkv.y;
        #pragma unroll
        for (int o = 16; o; o >>= 1) p += __shfl_xor_sync(0xffffffffu, p, o);
        sc[r] = (idx != l) ? p * 0.125f : -1e9f;
    }

    float m = sc[0];
    #pragma unroll
    for (int r = 1; r < R_; r++) m = fmaxf(m, sc[r]);
    float s = 0.0f;
    #pragma unroll
    for (int r = 0; r < R_; r++) { sc[r] = __expf(sc[r] - m); s += sc[r]; }
    float inv = 1.0f / s;

    float ax = 0.0f, ay = 0.0f;
    #pragma unroll
    for (int r = 0; r < R_; r++) {
        float a = sc[r] * inv;
        float2 rvv = *(const float2*)(rv + (h * R_ + r) * DK_ + lane * 2);
        float2 vg  = __half22float2(*(const __half2*)(vb + (size_t)(b * L_ + idxs[r]) * QSTR));
        ax = fmaf(a, vg.x + rvv.x, ax);
        ay = fmaf(a, vg.y + rvv.y, ay);
    }
    size_t coff = (size_t)(b * L_ + l) * D_ + h * DK_ + lane * 2;
    *(__half2*)(ctx + coff) = __floats2half2_rn(ax, ay);
}

// ---------------- host orchestration -------------------------------------
extern "C" void kernel_launch(void* const* d_in, const int* in_sizes, int n_in,
                              void* d_out, int out_size)
{
    const float* emb    = (const float*)d_in[0];
    const int*   pos    = (const int*)  d_in[1];
    const float* rel_q  = (const float*)d_in[2];
    const float* rel_k  = (const float*)d_in[3];
    const float* rel_v  = (const float*)d_in[4];
    const float* attn_w = (const float*)d_in[5];
    const float* attn_b = (const float*)d_in[6];
    const float* ff_w1  = (const float*)d_in[7];
    const float* ff_b1  = (const float*)d_in[8];
    const float* ff_w2  = (const float*)d_in[9];
    const float* ff_b2  = (const float*)d_in[10];
    const float* ln_g   = (const float*)d_in[11];
    const float* ln_b   = (const float*)d_in[12];
    const float* fin_g  = (const float*)d_in[13];
    const float* fin_b  = (const float*)d_in[14];
    float* out = (float*)d_out;

    float *x;
    __half *h, *qkv, *ctx, *ff, *wta, *wtf1, *wtf2;
    cudaGetSymbolAddress((void**)&x,    g_x);
    cudaGetSymbolAddress((void**)&h,    g_h);
    cudaGetSymbolAddress((void**)&qkv,  g_qkv);
    cudaGetSymbolAddress((void**)&ctx,  g_ctx);
    cudaGetSymbolAddress((void**)&ff,   g_ff);
    cudaGetSymbolAddress((void**)&wta,  g_wt_attn);
    cudaGetSymbolAddress((void**)&wtf1, g_wt_ff1);
    cudaGetSymbolAddress((void**)&wtf2, g_wt_ff2);

    static bool attr_done = false;
    if (!attr_done) {
        cudaFuncSetAttribute(tc_gemm, cudaFuncAttributeMaxDynamicSharedMemorySize, GEMM_SMEM);
        attr_done = true;
    }

    // ---- weight transposes: W[K][N] f32 -> Wt[N][K] f16 ----
    transpose_k<<<dim3(D_/32, D_/32, NL_*4), dim3(32,8)>>>(attn_w, wta,  D_, D_);
    transpose_k<<<dim3(F_/32, D_/32, NL_),   dim3(32,8)>>>(ff_w1,  wtf1, D_, F_);
    transpose_k<<<dim3(D_/32, F_/32, NL_),   dim3(32,8)>>>(ff_w2,  wtf2, F_, D_);

    dim3 gQKV(3*D_/128, ROWS_/128);   // (24, 16)
    dim3 gD(D_/128, ROWS_/128);       // (8, 16)
    dim3 gF(F_/128, ROWS_/128);       // (32, 16)
    int attn_blocks = (B_ * H_ * L_) / 8;

    for (int i = 0; i < NL_; i++) {
        const float* xin = (i == 0) ? emb : x;
        const __half* Wt = wta + (size_t)i * 4 * D_ * D_;
        const float* Bb = attn_b + (size_t)i * 4 * D_;

        ln_kernel<<<ROWS_, 256>>>(xin, ln_g + (size_t)(i*2) * D_, ln_b + (size_t)(i*2) * D_, h, 1);

        tc_gemm<<<gQKV, 256, GEMM_SMEM>>>(h, Wt, Bb, nullptr, qkv, ROWS_, QSTR, D_, 0, 1);

        attn_kernel<<<attn_blocks, 256>>>(qkv, pos, rel_q, rel_k, rel_v, ctx);

        tc_gemm<<<gD, 256, GEMM_SMEM>>>(ctx, Wt + (size_t)3*D_*D_, Bb + 3*D_, xin, x, ROWS_, D_, D_, 0, 0);

        ln_kernel<<<ROWS_, 256>>>(x, ln_g + (size_t)(i*2+1) * D_, ln_b + (size_t)(i*2+1) * D_, h, 1);

        tc_gemm<<<gF, 256, GEMM_SMEM>>>(h,  wtf1 + (size_t)i * D_ * F_, ff_b1 + (size_t)i * F_,
                                        nullptr, ff, ROWS_, F_, D_, 1, 1);
        tc_gemm<<<gD, 256, GEMM_SMEM>>>(ff, wtf2 + (size_t)i * F_ * D_, ff_b2 + (size_t)i * D_,
                                        x, x, ROWS_, D_, F_, 0, 0);
    }
    ln_kernel<<<ROWS_, 256>>>(x, fin_g, fin_b, out, 0);
}